// round 16
// baseline (speedup 1.0000x reference)
#include <cuda_runtime.h>
#include <math.h>
#include <stdint.h>

// Problem constants
#define TKN 2048          // B*N tokens
#define DM 1024           // model dim
#define NE 8              // experts
#define FFD 4096          // ffn dim
#define NH 16             // heads
#define HD 64             // head dim
#define PADROWS 3072      // token rows padded to 128 per expert segment
#define MAXTILES 24       // PADROWS/128

// ---------------- scratch (device globals; no allocation allowed) ----------------
__device__ float g_qkv[TKN * 3 * DM];
__device__ float g_ctx[TKN * DM];
__device__ float g_x[TKN * DM];
__device__ float g_tmp[8 * TKN * DM];     // up to 8 split-K partials
__device__ float g_h[TKN * FFD];
__device__ int   g_idx0[TKN];
__device__ int   g_idx1[TKN];
__device__ float g_gw0[TKN];
__device__ float g_gw1[TKN];
__device__ int   g_perm0[PADROWS];
__device__ int   g_perm1[PADROWS];
__device__ int   g_te0[MAXTILES];
__device__ int   g_te1[MAXTILES];

// pack two fp32 -> bf16x2 (first arg -> low half)
__device__ __forceinline__ uint32_t pack_bf16(float lo, float hi) {
    uint32_t r;
    asm("cvt.rn.bf16x2.f32 %0, %1, %2;" : "=r"(r) : "f"(hi), "f"(lo));
    return r;
}
__device__ __forceinline__ void mma_bf16(float& c0, float& c1, float& c2, float& c3,
                                         uint32_t a0, uint32_t a1, uint32_t a2, uint32_t a3,
                                         uint32_t b0, uint32_t b1) {
    asm volatile(
        "mma.sync.aligned.m16n8k16.row.col.f32.bf16.bf16.f32 "
        "{%0,%1,%2,%3}, {%4,%5,%6,%7}, {%8,%9}, {%0,%1,%2,%3};"
        : "+f"(c0), "+f"(c1), "+f"(c2), "+f"(c3)
        : "r"(a0), "r"(a1), "r"(a2), "r"(a3), "r"(b0), "r"(b1));
}
__device__ __forceinline__ uint32_t smem_addr(const void* p) {
    uint32_t a;
    asm("{ .reg .u64 t; cvta.to.shared.u64 t, %1; cvt.u32.u64 %0, t; }" : "=r"(a) : "l"(p));
    return a;
}
#define LDSM_X4(r0, r1, r2, r3, a) \
    asm volatile("ldmatrix.sync.aligned.m8n8.x4.shared.b16 {%0,%1,%2,%3}, [%4];" \
        : "=r"(r0), "=r"(r1), "=r"(r2), "=r"(r3) : "r"(a))
#define LDSM_T_X4(r0, r1, r2, r3, a) \
    asm volatile("ldmatrix.sync.aligned.m8n8.x4.trans.shared.b16 {%0,%1,%2,%3}, [%4];" \
        : "=r"(r0), "=r"(r1), "=r"(r2), "=r"(r3) : "r"(a))

// ---------------- gate (standalone, for attention gate on src) ----------------
__global__ void gate_kernel(const float* __restrict__ x, const float* __restrict__ Wg,
                            int* __restrict__ idx, float* __restrict__ gw) {
    int t = blockIdx.x;
    int warp = threadIdx.x >> 5, lane = threadIdx.x & 31;
    const float* xr = x + (size_t)t * DM;
    float s = 0.f;
    #pragma unroll 4
    for (int d = lane; d < DM; d += 32) s += xr[d] * Wg[d * NE + warp];
    #pragma unroll
    for (int o = 16; o; o >>= 1) s += __shfl_xor_sync(0xffffffffu, s, o);
    __shared__ float logits[NE];
    if (lane == 0) logits[warp] = s;
    __syncthreads();
    if (threadIdx.x == 0) {
        float best = logits[0]; int bi = 0;
        #pragma unroll
        for (int e = 1; e < NE; e++) if (logits[e] > best) { best = logits[e]; bi = e; }
        float sum = 0.f;
        #pragma unroll
        for (int e = 0; e < NE; e++) sum += expf(logits[e] - best);
        idx[t] = bi;
        gw[t] = 1.f / sum;
    }
}

// ---------------- scatter ----------------
__global__ void scatter_kernel(const int* __restrict__ idx, int* __restrict__ perm,
                               int* __restrict__ tile_expert) {
    __shared__ int cnt[NE];
    __shared__ int cur[NE];
    int tid = threadIdx.x;
    if (tid < NE) cnt[tid] = 0;
    for (int i = tid; i < PADROWS; i += blockDim.x) perm[i] = -1;
    __syncthreads();
    for (int t = tid; t < TKN; t += blockDim.x) atomicAdd(&cnt[idx[t]], 1);
    __syncthreads();
    if (tid == 0) {
        int c = 0;
        for (int e = 0; e < NE; e++) {
            cur[e] = c;
            int tiles = (cnt[e] + 127) >> 7;
            for (int i = 0; i < tiles; i++) tile_expert[(c >> 7) + i] = e;
            c += tiles << 7;
        }
        for (int i = c >> 7; i < MAXTILES; i++) tile_expert[i] = -1;
    }
    __syncthreads();
    for (int t = tid; t < TKN; t += blockDim.x) {
        int p = atomicAdd(&cur[idx[t]], 1);
        perm[p] = t;
    }
}

// ============ bf16 mma.sync MoE GEMM, BK=32, split-K, 512 threads, 16 warps ============
// CTA tile 128x128, warp tile 32x32 (4M x 4N warps). ldmatrix fragments.
// A smem: m-major pairs, row stride 20 words. B smem: bf16 [k][n], row stride 136 halves.
#define ASTRW 20
#define ASTGW (128 * ASTRW)      // 2560 words
#define BSTRH 136
#define BSTGW (32 * BSTRH / 2)   // 2176 words

__global__ void __launch_bounds__(512, 2)
moe_gemm_mma(const float* __restrict__ In, const float* __restrict__ W,
             const float* __restrict__ bias, const float* __restrict__ gw,
             const int* __restrict__ perm, const int* __restrict__ tile_expert,
             float* __restrict__ Out, int Ktot, int Nout, int gelu_flag, int klen) {
    int e = tile_expert[blockIdx.y];
    if (e < 0) return;
    __shared__ uint32_t SA[2][ASTGW];
    __shared__ uint32_t SB[2][BSTGW];

    int tid = threadIdx.x, wid = tid >> 5, lane = tid & 31;
    int g = lane >> 2, tg = lane & 3;
    int warp_m = wid & 3, warp_n = wid >> 2;   // 4 x 4 warps
    int row0 = blockIdx.y << 7, col0 = blockIdx.x << 7;
    int k0off = blockIdx.z * klen;
    float* OutZ = Out + (size_t)blockIdx.z * TKN * Nout;
    float bsel = (blockIdx.z == 0) ? 1.f : 0.f;

    // A loader: 4 threads per row; thread covers 8 floats (4 pair-words)
    int mS = tid & 127;
    int quarter = tid >> 7;                   // 0..3
    int tokA = perm[row0 + mS];
    const float* aptr = (tokA >= 0) ? (In + (size_t)tokA * Ktot + k0off + (quarter << 3)) : In;
    uint32_t* adst0 = &SA[0][mS * ASTRW + (quarter << 2)];
    // B loader: 2 k-rows per thread, 4 n each
    int k2 = (tid >> 5) << 1;                 // 0..30
    int nB4 = (tid & 31) << 2;
    const float* bptr = W + ((size_t)e * Ktot + k0off + k2) * Nout + col0 + nB4;
    uint16_t* bdst0 = (uint16_t*)&SB[0][0] + (k2 * BSTRH + nB4);

    // ldmatrix per-lane addresses
    uint32_t sa0 = smem_addr(&SA[0][0]);
    uint32_t sb0 = smem_addr(&SB[0][0]);
    int mAl = warp_m * 32 + (lane & 15);
    uint32_t a_off = sa0 + (uint32_t)(mAl * ASTRW + ((lane >> 4) << 2)) * 4u;
    int kBl = (lane & 7) + ((lane >> 3) & 1) * 8;
    uint32_t b_off = sb0 + (uint32_t)(kBl * BSTRH + warp_n * 32 + ((lane >> 4) << 3)) * 2u;

    float acc[2][4][4];
    #pragma unroll
    for (int mi = 0; mi < 2; mi++)
        #pragma unroll
        for (int ni = 0; ni < 4; ni++)
            #pragma unroll
            for (int q = 0; q < 4; q++) acc[mi][ni][q] = 0.f;

    int nchunk = klen >> 5;

    // ---- prologue: chunk 0 into stage 0 ----
    {
        float4 av0 = make_float4(0.f,0.f,0.f,0.f), av1 = av0;
        if (tokA >= 0) { av0 = *(const float4*)(aptr); av1 = *(const float4*)(aptr + 4); }
        float4 bv0 = *(const float4*)(bptr);
        float4 bv1 = *(const float4*)(bptr + Nout);
        *(uint4*)adst0 = make_uint4(pack_bf16(av0.x, av0.y), pack_bf16(av0.z, av0.w),
                                    pack_bf16(av1.x, av1.y), pack_bf16(av1.z, av1.w));
        *(uint2*)bdst0 = make_uint2(pack_bf16(bv0.x, bv0.y), pack_bf16(bv0.z, bv0.w));
        *(uint2*)(bdst0 + BSTRH) = make_uint2(pack_bf16(bv1.x, bv1.y), pack_bf16(bv1.z, bv1.w));
    }
    __syncthreads();

    for (int c = 0; c < nchunk; c++) {
        int buf = c & 1;
        bool has_next = (c + 1) < nchunk;
        uint32_t aw[4], bw[4];
        if (has_next) {
            int k0 = (c + 1) << 5;
            float4 av0 = make_float4(0.f,0.f,0.f,0.f), av1 = av0;
            if (tokA >= 0) { av0 = *(const float4*)(aptr + k0); av1 = *(const float4*)(aptr + k0 + 4); }
            const float* bp = bptr + (size_t)k0 * Nout;
            float4 bv0 = *(const float4*)(bp);
            float4 bv1 = *(const float4*)(bp + Nout);
            aw[0] = pack_bf16(av0.x, av0.y); aw[1] = pack_bf16(av0.z, av0.w);
            aw[2] = pack_bf16(av1.x, av1.y); aw[3] = pack_bf16(av1.z, av1.w);
            bw[0] = pack_bf16(bv0.x, bv0.y); bw[1] = pack_bf16(bv0.z, bv0.w);
            bw[2] = pack_bf16(bv1.x, bv1.y); bw[3] = pack_bf16(bv1.z, bv1.w);
        }

        // ---- compute chunk c: 2 ksteps ----
        uint32_t abase = a_off + (uint32_t)buf * (ASTGW * 4);
        uint32_t bbase = b_off + (uint32_t)buf * (BSTGW * 4);
        #pragma unroll
        for (int ks = 0; ks < 2; ks++) {
            uint32_t a[2][4];
            LDSM_X4(a[0][0], a[0][1], a[0][2], a[0][3], abase + ks * 32);
            LDSM_X4(a[1][0], a[1][1], a[1][2], a[1][3], abase + 1280 + ks * 32);
            #pragma unroll
            for (int nip = 0; nip < 2; nip++) {
                uint32_t bA0, bA1, bB0, bB1;
                LDSM_T_X4(bA0, bA1, bB0, bB1, bbase + ks * 4352 + nip * 32);
                int niA = 2 * nip, niB = 2 * nip + 1;
                mma_bf16(acc[0][niA][0], acc[0][niA][1], acc[0][niA][2], acc[0][niA][3],
                         a[0][0], a[0][1], a[0][2], a[0][3], bA0, bA1);
                mma_bf16(acc[1][niA][0], acc[1][niA][1], acc[1][niA][2], acc[1][niA][3],
                         a[1][0], a[1][1], a[1][2], a[1][3], bA0, bA1);
                mma_bf16(acc[0][niB][0], acc[0][niB][1], acc[0][niB][2], acc[0][niB][3],
                         a[0][0], a[0][1], a[0][2], a[0][3], bB0, bB1);
                mma_bf16(acc[1][niB][0], acc[1][niB][1], acc[1][niB][2], acc[1][niB][3],
                         a[1][0], a[1][1], a[1][2], a[1][3], bB0, bB1);
            }
        }

        if (has_next) {
            int nb = buf ^ 1;
            uint32_t* adst = adst0 + nb * ASTGW;
            uint16_t* bdst = bdst0 + nb * (BSTGW * 2);
            *(uint4*)adst = make_uint4(aw[0], aw[1], aw[2], aw[3]);
            *(uint2*)bdst = make_uint2(bw[0], bw[1]);
            *(uint2*)(bdst + BSTRH) = make_uint2(bw[2], bw[3]);
            __syncthreads();
        }
    }

    // ---- epilogue: warp tile 32x32 ----
    int tok[4]; float gwv[4];
    #pragma unroll
    for (int q = 0; q < 4; q++) {
        int r = row0 + warp_m * 32 + g + q * 8;
        tok[q] = perm[r];
        gwv[q] = (tok[q] >= 0) ? gw[tok[q]] : 0.f;
    }
    #pragma unroll
    for (int ni = 0; ni < 4; ni++) {
        int col = col0 + warp_n * 32 + ni * 8 + 2 * tg;
        float2 bs2 = *(const float2*)&bias[(size_t)e * Nout + col];
        bs2.x *= bsel; bs2.y *= bsel;
        #pragma unroll
        for (int mi = 0; mi < 2; mi++) {
            #pragma unroll
            for (int half2 = 0; half2 < 2; half2++) {
                int q = mi * 2 + half2;
                if (tok[q] < 0) continue;
                float v0 = (acc[mi][ni][half2 * 2 + 0] + bs2.x) * gwv[q];
                float v1 = (acc[mi][ni][half2 * 2 + 1] + bs2.y) * gwv[q];
                if (gelu_flag) {
                    float c0 = v0 + 0.044715f * v0 * v0 * v0;
                    v0 = 0.5f * v0 * (1.f + tanhf(0.7978845608028654f * c0));
                    float c1 = v1 + 0.044715f * v1 * v1 * v1;
                    v1 = 0.5f * v1 * (1.f + tanhf(0.7978845608028654f * c1));
                }
                *(float2*)&OutZ[(size_t)tok[q] * Nout + col] = make_float2(v0, v1);
            }
        }
    }
}

// ============ flash attention FA2: BQ=128, BK=64, bf16, ldmatrix (R15 proven) ============
#define QSTR 36
#define ATT5_SMEM_WORDS ((128 + 64 + 64) * QSTR + 64)

__global__ void __launch_bounds__(256, 2)
attn_mma(const float* __restrict__ qkv, const unsigned char* __restrict__ mask,
         float* __restrict__ ctx) {
    extern __shared__ uint32_t sm4[];
    uint32_t* Qs = sm4;
    uint32_t* Ks = Qs + 128 * QSTR;
    uint32_t* Vt = Ks + 64 * QSTR;
    float* maskS = (float*)(Vt + 64 * QSTR);

    int bh = blockIdx.y;
    int b = bh >> 4, h = bh & 15;
    int n0 = blockIdx.x << 7;
    int tid = threadIdx.x, lane = tid & 31, wid = tid >> 5;
    int g = lane >> 2, tg = lane & 3;
    int am0 = wid * 16 + g;

    uint32_t qaddr = smem_addr(Qs) +
        (uint32_t)((wid * 16 + (lane & 15)) * QSTR + ((lane >> 4) << 2)) * 4u;
    uint32_t bl_row = (uint32_t)((lane & 7) + ((lane >> 4) << 3));
    uint32_t bl_col = (uint32_t)(((lane >> 3) & 1) << 2);
    uint32_t kaddr = smem_addr(Ks) + (bl_row * QSTR + bl_col) * 4u;
    uint32_t vaddr = smem_addr(Vt) + (bl_row * QSTR + bl_col) * 4u;

    {
        int qrow = tid & 127, qd0 = (tid >> 7) << 5;
        int qp0 = qd0 >> 1;
        const float* qp = qkv + (size_t)(b * 1024 + n0 + qrow) * 3072 + h * 64 + qd0;
        #pragma unroll
        for (int i = 0; i < 8; i++) {
            float4 v = *(const float4*)(qp + 4 * i);
            Qs[qrow * QSTR + qp0 + 2 * i]     = pack_bf16(v.x, v.y);
            Qs[qrow * QSTR + qp0 + 2 * i + 1] = pack_bf16(v.z, v.w);
        }
    }

    float o[8][4];
    #pragma unroll
    for (int ni = 0; ni < 8; ni++)
        #pragma unroll
        for (int q = 0; q < 4; q++) o[ni][q] = 0.f;
    float m0 = -1e30f, m1 = -1e30f, l0 = 0.f, l1 = 0.f;

    int krow = tid & 63, kd0 = (tid >> 6) << 4;
    int vkp = tid & 31, vd0 = (tid >> 5) << 3;

    for (int kt = 0; kt < 16; kt++) {
        {
            const float* kbase = qkv + (size_t)(b * 1024 + kt * 64 + krow) * 3072 + h * 64 + 1024 + kd0;
            int kp0 = kd0 >> 1;
            #pragma unroll
            for (int i = 0; i < 4; i++) {
                float4 kv = *(const float4*)(kbase + 4 * i);
                Ks[krow * QSTR + kp0 + 2 * i]     = pack_bf16(kv.x, kv.y);
                Ks[krow * QSTR + kp0 + 2 * i + 1] = pack_bf16(kv.z, kv.w);
            }
            const float* v0p = qkv + (size_t)(b * 1024 + kt * 64 + 2 * vkp) * 3072 + h * 64 + 2048 + vd0;
            const float* v1p = v0p + 3072;
            float4 va0 = *(const float4*)(v0p);
            float4 va1 = *(const float4*)(v0p + 4);
            float4 vb0 = *(const float4*)(v1p);
            float4 vb1 = *(const float4*)(v1p + 4);
            Vt[(vd0 + 0) * QSTR + vkp] = pack_bf16(va0.x, vb0.x);
            Vt[(vd0 + 1) * QSTR + vkp] = pack_bf16(va0.y, vb0.y);
            Vt[(vd0 + 2) * QSTR + vkp] = pack_bf16(va0.z, vb0.z);
            Vt[(vd0 + 3) * QSTR + vkp] = pack_bf16(va0.w, vb0.w);
            Vt[(vd0 + 4) * QSTR + vkp] = pack_bf16(va1.x, vb1.x);
            Vt[(vd0 + 5) * QSTR + vkp] = pack_bf16(va1.y, vb1.y);
            Vt[(vd0 + 6) * QSTR + vkp] = pack_bf16(va1.z, vb1.z);
            Vt[(vd0 + 7) * QSTR + vkp] = pack_bf16(va1.w, vb1.w);
            if (tid < 64)
                maskS[tid] = mask[b * 1024 + kt * 64 + tid] ? -10000.f : 0.f;
        }
        __syncthreads();

        float s[8][4];
        #pragma unroll
        for (int ni = 0; ni < 8; ni++)
            #pragma unroll
            for (int q = 0; q < 4; q++) s[ni][q] = 0.f;
        #pragma unroll
        for (int kb8 = 0; kb8 < 4; kb8++) {
            uint32_t a0, a1, a2, a3;
            LDSM_X4(a0, a1, a2, a3, qaddr + kb8 * 32);
            #pragma unroll
            for (int nip = 0; nip < 4; nip++) {
                uint32_t b0, b1, c0, c1;
                LDSM_X4(b0, b1, c0, c1, kaddr + nip * (16 * QSTR * 4) + kb8 * 32);
                int niA = 2 * nip, niB = 2 * nip + 1;
                mma_bf16(s[niA][0], s[niA][1], s[niA][2], s[niA][3], a0, a1, a2, a3, b0, b1);
                mma_bf16(s[niB][0], s[niB][1], s[niB][2], s[niB][3], a0, a1, a2, a3, c0, c1);
            }
        }
        #pragma unroll
        for (int ni = 0; ni < 8; ni++) {
            int c0 = ni * 8 + 2 * tg;
            float mv0 = maskS[c0], mv1 = maskS[c0 + 1];
            s[ni][0] = s[ni][0] * 0.125f + mv0;
            s[ni][1] = s[ni][1] * 0.125f + mv1;
            s[ni][2] = s[ni][2] * 0.125f + mv0;
            s[ni][3] = s[ni][3] * 0.125f + mv1;
        }

        float rm0 = -1e30f, rm1 = -1e30f;
        #pragma unroll
        for (int ni = 0; ni < 8; ni++) {
            rm0 = fmaxf(rm0, fmaxf(s[ni][0], s[ni][1]));
            rm1 = fmaxf(rm1, fmaxf(s[ni][2], s[ni][3]));
        }
        rm0 = fmaxf(rm0, __shfl_xor_sync(0xffffffffu, rm0, 1));
        rm0 = fmaxf(rm0, __shfl_xor_sync(0xffffffffu, rm0, 2));
        rm1 = fmaxf(rm1, __shfl_xor_sync(0xffffffffu, rm1, 1));
        rm1 = fmaxf(rm1, __shfl_xor_sync(0xffffffffu, rm1, 2));
        float mn0 = fmaxf(m0, rm0), mn1 = fmaxf(m1, rm1);
        float sc0 = __expf(m0 - mn0), sc1 = __expf(m1 - mn1);
        m0 = mn0; m1 = mn1;

        float ps0 = 0.f, ps1 = 0.f;
        #pragma unroll
        for (int ni = 0; ni < 8; ni++) {
            s[ni][0] = __expf(s[ni][0] - mn0);
            s[ni][1] = __expf(s[ni][1] - mn0);
            s[ni][2] = __expf(s[ni][2] - mn1);
            s[ni][3] = __expf(s[ni][3] - mn1);
            ps0 += s[ni][0] + s[ni][1];
            ps1 += s[ni][2] + s[ni][3];
        }
        ps0 += __shfl_xor_sync(0xffffffffu, ps0, 1);
        ps0 += __shfl_xor_sync(0xffffffffu, ps0, 2);
        ps1 += __shfl_xor_sync(0xffffffffu, ps1, 1);
        ps1 += __shfl_xor_sync(0xffffffffu, ps1, 2);
        l0 = l0 * sc0 + ps0;
        l1 = l1 * sc1 + ps1;

        #pragma unroll
        for (int ni = 0; ni < 8; ni++) {
            o[ni][0] *= sc0; o[ni][1] *= sc0;
            o[ni][2] *= sc1; o[ni][3] *= sc1;
        }

        #pragma unroll
        for (int kk = 0; kk < 4; kk++) {
            uint32_t a0 = pack_bf16(s[2 * kk][0],     s[2 * kk][1]);
            uint32_t a1 = pack_bf16(s[2 * kk][2],     s[2 * kk][3]);
            uint32_t a2 = pack_bf16(s[2 * kk + 1][0], s[2 * kk + 1][1]);
            uint32_t a3 = pack_bf16(s[2 * kk + 1][2], s[2 * kk + 1][3]);
            #pragma unroll
            for (int nip = 0; nip < 4; nip++) {
                uint32_t b0, b1, c0, c1;
                LDSM_X4(b0, b1, c0, c1, vaddr + nip * (16 * QSTR * 4) + kk * 32);
                int niA = 2 * nip, niB = 2 * nip + 1;
                mma_bf16(o[niA][0], o[niA][1], o[niA][2], o[niA][3], a0, a1, a2, a3, b0, b1);
                mma_bf16(o[niB][0], o[niB][1], o[niB][2], o[niB][3], a0, a1, a2, a3, c0, c1);
            }
        }
        __syncthreads();
    }

    float inv0 = 1.f / l0, inv1 = 1.f / l1;
    int t0 = b * 1024 + n0 + am0;
    int t1 = t0 + 8;
    #pragma unroll
    for (int ni = 0; ni < 8; ni++) {
        int c = ni * 8 + 2 * tg;
        *(float2*)&ctx[(size_t)t0 * 1024 + h * 64 + c] =
            make_float2(o[ni][0] * inv0, o[ni][1] * inv0);
        *(float2*)&ctx[(size_t)t1 * 1024 + h * 64 + c] =
            make_float2(o[ni][2] * inv1, o[ni][3] * inv1);
    }
}

// ---------------- residual + layernorm (+ optional fused top-1 gate) ----------------
__global__ void __launch_bounds__(256)
ln_kernel(const float* __restrict__ a, const float* __restrict__ parts, int nb,
          const float* __restrict__ s, const float* __restrict__ bias,
          float* __restrict__ out,
          const float* __restrict__ Wg, int* __restrict__ gidx, float* __restrict__ ggw) {
    int t = blockIdx.x;
    int base = threadIdx.x << 2;
    size_t off = (size_t)t * DM + base;
    float4 av = *(const float4*)(a + off);
    float v[4] = {av.x, av.y, av.z, av.w};
    for (int p = 0; p < nb; p++) {
        float4 c = *(const float4*)(parts + (size_t)p * TKN * DM + off);
        v[0] += c.x; v[1] += c.y; v[2] += c.z; v[3] += c.w;
    }
    float s1 = v[0] + v[1] + v[2] + v[3];
    float s2 = v[0] * v[0] + v[1] * v[1] + v[2] * v[2] + v[3] * v[3];
    #pragma unroll
    for (int o = 16; o; o >>= 1) {
        s1 += __shfl_xor_sync(0xffffffffu, s1, o);
        s2 += __shfl_xor_sync(0xffffffffu, s2, o);
    }
    __shared__ float w1[8], w2[8];
    __shared__ float wlog[8][NE];
    __shared__ float sh_mean, sh_inv;
    int warp = threadIdx.x >> 5, lane = threadIdx.x & 31;
    if (lane == 0) { w1[warp] = s1; w2[warp] = s2; }
    __syncthreads();
    if (threadIdx.x == 0) {
        float A = 0.f, B = 0.f;
        #pragma unroll
        for (int i = 0; i < 8; i++) { A += w1[i]; B += w2[i]; }
        float mean = A * (1.f / DM);
        float var = B * (1.f / DM) - mean * mean;
        sh_mean = mean;
        sh_inv = rsqrtf(var + 1e-5f);
    }
    __syncthreads();
    float mean = sh_mean, inv = sh_inv;
    float4 sv = *(const float4*)(s + base);
    float4 biv = *(const float4*)(bias + base);
    float xr[4];
    xr[0] = (v[0] - mean) * inv * sv.x + biv.x;
    xr[1] = (v[1] - mean) * inv * sv.y + biv.y;
    xr[2] = (v[2] - mean) * inv * sv.z + biv.z;
    xr[3] = (v[3] - mean) * inv * sv.w + biv.w;
    *(float4*)(out + off) = make_float4(xr[0], xr[1], xr[2], xr[3]);

    if (Wg) {
        float lg[NE];
        #pragma unroll
        for (int e2 = 0; e2 < NE; e2++) lg[e2] = 0.f;
        #pragma unroll
        for (int j = 0; j < 4; j++) {
            float4 w0 = *(const float4*)&Wg[(base + j) * NE];
            float4 wq = *(const float4*)&Wg[(base + j) * NE + 4];
            lg[0] += xr[j] * w0.x; lg[1] += xr[j] * w0.y;
            lg[2] += xr[j] * w0.z; lg[3] += xr[j] * w0.w;
            lg[4] += xr[j] * wq.x; lg[5] += xr[j] * wq.y;
            lg[6] += xr[j] * wq.z; lg[7] += xr[j] * wq.w;
        }
        #pragma unroll
        for (int e2 = 0; e2 < NE; e2++) {
            float q = lg[e2];
            #pragma unroll
            for (int o = 16; o; o >>= 1) q += __shfl_xor_sync(0xffffffffu, q, o);
            if (lane == 0) wlog[warp][e2] = q;
        }
        __syncthreads();
        if (threadIdx.x == 0) {
            float logits[NE];
            #pragma unroll
            for (int e2 = 0; e2 < NE; e2++) {
                float q = 0.f;
                #pragma unroll
                for (int w = 0; w < 8; w++) q += wlog[w][e2];
                logits[e2] = q;
            }
            float best = logits[0]; int bi = 0;
            #pragma unroll
            for (int e2 = 1; e2 < NE; e2++)
                if (logits[e2] > best) { best = logits[e2]; bi = e2; }
            float sum = 0.f;
            #pragma unroll
            for (int e2 = 0; e2 < NE; e2++) sum += expf(logits[e2] - best);
            gidx[t] = bi;
            ggw[t] = 1.f / sum;
        }
    }
}

// ---------------- launch ----------------
extern "C" void kernel_launch(void* const* d_in, const int* in_sizes, int n_in,
                              void* d_out, int out_size) {
    const float* src     = (const float*)d_in[0];
    const unsigned char* mask = (const unsigned char*)d_in[1];
    const float* Wg_attn = (const float*)d_in[2];
    const float* Wqkv    = (const float*)d_in[3];
    const float* bqkv    = (const float*)d_in[4];
    const float* Wo      = (const float*)d_in[5];
    const float* bo      = (const float*)d_in[6];
    const float* Wg_ffn  = (const float*)d_in[7];
    const float* W1      = (const float*)d_in[8];
    const float* b1      = (const float*)d_in[9];
    const float* W2      = (const float*)d_in[10];
    const float* b2      = (const float*)d_in[11];
    const float* ln1_s   = (const float*)d_in[12];
    const float* ln1_b   = (const float*)d_in[13];
    const float* ln2_s   = (const float*)d_in[14];
    const float* ln2_b   = (const float*)d_in[15];
    float* out = (float*)d_out;

    float *qkv, *ctx, *x, *tmp, *hbuf, *gw0, *gw1;
    int *idx0, *idx1, *perm0, *perm1, *te0, *te1;
    cudaGetSymbolAddress((void**)&qkv,  g_qkv);
    cudaGetSymbolAddress((void**)&ctx,  g_ctx);
    cudaGetSymbolAddress((void**)&x,    g_x);
    cudaGetSymbolAddress((void**)&tmp,  g_tmp);
    cudaGetSymbolAddress((void**)&hbuf, g_h);
    cudaGetSymbolAddress((void**)&gw0,  g_gw0);
    cudaGetSymbolAddress((void**)&gw1,  g_gw1);
    cudaGetSymbolAddress((void**)&idx0, g_idx0);
    cudaGetSymbolAddress((void**)&idx1, g_idx1);
    cudaGetSymbolAddress((void**)&perm0, g_perm0);
    cudaGetSymbolAddress((void**)&perm1, g_perm1);
    cudaGetSymbolAddress((void**)&te0,  g_te0);
    cudaGetSymbolAddress((void**)&te1,  g_te1);

    int att_smem = ATT5_SMEM_WORDS * (int)sizeof(uint32_t);
    cudaFuncSetAttribute(attn_mma, cudaFuncAttributeMaxDynamicSharedMemorySize, att_smem);

    // 1. attention gate + grouping
    gate_kernel<<<TKN, 256>>>(src, Wg_attn, idx0, gw0);
    scatter_kernel<<<1, 256>>>(idx0, perm0, te0);
    // 2. QKV projection
    moe_gemm_mma<<<dim3(3 * DM / 128, MAXTILES, 1), 512>>>(
        src, Wqkv, bqkv, gw0, perm0, te0, qkv, DM, 3 * DM, 0, DM);
    // 3. attention (FA2, ldmatrix)
    attn_mma<<<dim3(1024 / 128, 2 * NH), 256, att_smem>>>(qkv, mask, ctx);
    // 4. output projection, split-K x4
    moe_gemm_mma<<<dim3(DM / 128, MAXTILES, 4), 512>>>(
        ctx, Wo, bo, gw0, perm0, te0, tmp, DM, DM, 0, DM / 4);
    // 5. x = LN1(src + 4 partials) + fused FFN gate
    ln_kernel<<<TKN, 256>>>(src, tmp, 4, ln1_s, ln1_b, x, Wg_ffn, idx1, gw1);
    // 6. FFN grouping
    scatter_kernel<<<1, 256>>>(idx1, perm1, te1);
    // 7. h = gelu(gated W1)
    moe_gemm_mma<<<dim3(FFD / 128, MAXTILES, 1), 512>>>(
        x, W1, b1, gw1, perm1, te1, hbuf, DM, FFD, 1, DM);
    // 8. ffn = gated W2, split-K x8
    moe_gemm_mma<<<dim3(DM / 128, MAXTILES, 8), 512>>>(
        hbuf, W2, b2, gw1, perm1, te1, tmp, FFD, DM, 0, FFD / 8);
    // 9. out = LN2(x + 8 partials), no gate
    ln_kernel<<<TKN, 256>>>(x, tmp, 8, ln2_s, ln2_b, out, nullptr, nullptr, nullptr);
}

// round 17
// speedup vs baseline: 1.5171x; 1.5171x over previous
#include <cuda_runtime.h>
#include <math.h>
#include <stdint.h>

// Problem constants
#define TKN 2048          // B*N tokens
#define DM 1024           // model dim
#define NE 8              // experts
#define FFD 4096          // ffn dim
#define NH 16             // heads
#define HD 64             // head dim
#define PADROWS 3072      // token rows padded to 128 per expert segment
#define MAXTILES 24       // PADROWS/128

// ---------------- scratch (device globals; no allocation allowed) ----------------
__device__ uint32_t g_srcb[TKN * DM / 2];       // src in bf16 pairs
__device__ uint32_t g_qkvb[TKN * 3 * DM / 2];   // qkv in bf16 pairs
__device__ uint32_t g_ctxb[TKN * DM / 2];       // ctx in bf16 pairs
__device__ float    g_x[TKN * DM];
__device__ uint32_t g_xb[TKN * DM / 2];         // x in bf16 pairs
__device__ float    g_tmp[8 * TKN * DM];        // split-K fp32 partials
__device__ uint32_t g_hb[TKN * FFD / 2];        // gelu output in bf16 pairs
__device__ int   g_idx0[TKN];
__device__ int   g_idx1[TKN];
__device__ float g_gw0[TKN];
__device__ float g_gw1[TKN];
__device__ int   g_perm0[PADROWS];
__device__ int   g_perm1[PADROWS];
__device__ int   g_te0[MAXTILES];
__device__ int   g_te1[MAXTILES];

// pack two fp32 -> bf16x2 (first arg -> low half)
__device__ __forceinline__ uint32_t pack_bf16(float lo, float hi) {
    uint32_t r;
    asm("cvt.rn.bf16x2.f32 %0, %1, %2;" : "=r"(r) : "f"(hi), "f"(lo));
    return r;
}
__device__ __forceinline__ void mma_bf16(float& c0, float& c1, float& c2, float& c3,
                                         uint32_t a0, uint32_t a1, uint32_t a2, uint32_t a3,
                                         uint32_t b0, uint32_t b1) {
    asm volatile(
        "mma.sync.aligned.m16n8k16.row.col.f32.bf16.bf16.f32 "
        "{%0,%1,%2,%3}, {%4,%5,%6,%7}, {%8,%9}, {%0,%1,%2,%3};"
        : "+f"(c0), "+f"(c1), "+f"(c2), "+f"(c3)
        : "r"(a0), "r"(a1), "r"(a2), "r"(a3), "r"(b0), "r"(b1));
}
__device__ __forceinline__ uint32_t smem_addr(const void* p) {
    uint32_t a;
    asm("{ .reg .u64 t; cvta.to.shared.u64 t, %1; cvt.u32.u64 %0, t; }" : "=r"(a) : "l"(p));
    return a;
}
#define LDSM_X4(r0, r1, r2, r3, a) \
    asm volatile("ldmatrix.sync.aligned.m8n8.x4.shared.b16 {%0,%1,%2,%3}, [%4];" \
        : "=r"(r0), "=r"(r1), "=r"(r2), "=r"(r3) : "r"(a))
#define LDSM_T_X4(r0, r1, r2, r3, a) \
    asm volatile("ldmatrix.sync.aligned.m8n8.x4.trans.shared.b16 {%0,%1,%2,%3}, [%4];" \
        : "=r"(r0), "=r"(r1), "=r"(r2), "=r"(r3) : "r"(a))

// ---------------- fp32 -> bf16 pair conversion (grid of 2048x256 covers 2M floats) ----------------
__global__ void cvtb_kernel(const float* __restrict__ in, uint32_t* __restrict__ out) {
    int i = blockIdx.x * blockDim.x + threadIdx.x;   // 0 .. 524287
    float4 v = *(const float4*)(in + 4 * (size_t)i);
    *(uint2*)&out[2 * (size_t)i] = make_uint2(pack_bf16(v.x, v.y), pack_bf16(v.z, v.w));
}

// ---------------- gate (standalone, attention gate on src) ----------------
__global__ void gate_kernel(const float* __restrict__ x, const float* __restrict__ Wg,
                            int* __restrict__ idx, float* __restrict__ gw) {
    int t = blockIdx.x;
    int warp = threadIdx.x >> 5, lane = threadIdx.x & 31;
    const float* xr = x + (size_t)t * DM;
    float s = 0.f;
    #pragma unroll 4
    for (int d = lane; d < DM; d += 32) s += xr[d] * Wg[d * NE + warp];
    #pragma unroll
    for (int o = 16; o; o >>= 1) s += __shfl_xor_sync(0xffffffffu, s, o);
    __shared__ float logits[NE];
    if (lane == 0) logits[warp] = s;
    __syncthreads();
    if (threadIdx.x == 0) {
        float best = logits[0]; int bi = 0;
        #pragma unroll
        for (int e = 1; e < NE; e++) if (logits[e] > best) { best = logits[e]; bi = e; }
        float sum = 0.f;
        #pragma unroll
        for (int e = 0; e < NE; e++) sum += expf(logits[e] - best);
        idx[t] = bi;
        gw[t] = 1.f / sum;
    }
}

// ---------------- scatter ----------------
__global__ void scatter_kernel(const int* __restrict__ idx, int* __restrict__ perm,
                               int* __restrict__ tile_expert) {
    __shared__ int cnt[NE];
    __shared__ int cur[NE];
    int tid = threadIdx.x;
    if (tid < NE) cnt[tid] = 0;
    for (int i = tid; i < PADROWS; i += blockDim.x) perm[i] = -1;
    __syncthreads();
    for (int t = tid; t < TKN; t += blockDim.x) atomicAdd(&cnt[idx[t]], 1);
    __syncthreads();
    if (tid == 0) {
        int c = 0;
        for (int e = 0; e < NE; e++) {
            cur[e] = c;
            int tiles = (cnt[e] + 127) >> 7;
            for (int i = 0; i < tiles; i++) tile_expert[(c >> 7) + i] = e;
            c += tiles << 7;
        }
        for (int i = c >> 7; i < MAXTILES; i++) tile_expert[i] = -1;
    }
    __syncthreads();
    for (int t = tid; t < TKN; t += blockDim.x) {
        int p = atomicAdd(&cur[idx[t]], 1);
        perm[p] = t;
    }
}

// ============ bf16 mma.sync MoE GEMM (R15 shape): BK=32, split-K, ldmatrix ============
// A input is bf16 pair-words. B = fp32 weights (cvt at STS). Optional bf16 output.
#define ASTRW 20
#define ASTGW (128 * ASTRW)      // 2560 words
#define BSTRH 136
#define BSTGW (32 * BSTRH / 2)   // 2176 words

__global__ void __launch_bounds__(256, 2)
moe_gemm_mma(const uint32_t* __restrict__ In, const float* __restrict__ W,
             const float* __restrict__ bias, const float* __restrict__ gw,
             const int* __restrict__ perm, const int* __restrict__ tile_expert,
             float* __restrict__ Out, int Ktot, int Nout, int gelu_flag, int klen,
             int out_bf16) {
    int e = tile_expert[blockIdx.y];
    if (e < 0) return;
    __shared__ uint32_t SA[2][ASTGW];
    __shared__ uint32_t SB[2][BSTGW];

    int tid = threadIdx.x, wid = tid >> 5, lane = tid & 31;
    int g = lane >> 2, tg = lane & 3;
    int warp_m = wid & 3, warp_n = wid >> 2;
    int row0 = blockIdx.y << 7, col0 = blockIdx.x << 7;
    int k0off = blockIdx.z * klen;
    float* OutZ = Out + (size_t)blockIdx.z * TKN * Nout;
    float bsel = (blockIdx.z == 0) ? 1.f : 0.f;

    // A loader: thread -> row mS, k-half (16 halves = 8 pair-words, contiguous)
    int mS = tid & 127;
    int half = tid >> 7;
    int tokA = perm[row0 + mS];
    const uint32_t* aptr = (tokA >= 0)
        ? (In + (size_t)tokA * (Ktot >> 1) + (k0off >> 1) + (half << 3)) : In;
    uint32_t* adst0 = &SA[0][mS * ASTRW + (half << 3)];
    // B loader: thread -> 4 k-rows, 4 n each (one STS.64 per row)
    int k4 = (tid >> 5) << 2;
    int nB4 = (tid & 31) << 2;
    const float* bptr = W + ((size_t)e * Ktot + k0off + k4) * Nout + col0 + nB4;
    uint16_t* bdst0 = (uint16_t*)&SB[0][0] + (k4 * BSTRH + nB4);

    uint32_t sa0 = smem_addr(&SA[0][0]);
    uint32_t sb0 = smem_addr(&SB[0][0]);
    int mAl = warp_m * 32 + (lane & 15);
    uint32_t a_off = sa0 + (uint32_t)(mAl * ASTRW + ((lane >> 4) << 2)) * 4u;
    int kBl = (lane & 7) + ((lane >> 3) & 1) * 8;
    uint32_t b_off = sb0 + (uint32_t)(kBl * BSTRH + warp_n * 64 + ((lane >> 4) << 3)) * 2u;

    float acc[2][8][4];
    #pragma unroll
    for (int mi = 0; mi < 2; mi++)
        #pragma unroll
        for (int ni = 0; ni < 8; ni++)
            #pragma unroll
            for (int q = 0; q < 4; q++) acc[mi][ni][q] = 0.f;

    int nchunk = klen >> 5;

    // ---- prologue: chunk 0 into stage 0 ----
    {
        uint4 aw0 = make_uint4(0u,0u,0u,0u), aw1 = aw0;
        if (tokA >= 0) { aw0 = *(const uint4*)(aptr); aw1 = *(const uint4*)(aptr + 4); }
        float4 bv[4];
        #pragma unroll
        for (int i = 0; i < 4; i++)
            bv[i] = *(const float4*)(bptr + (size_t)i * Nout);
        *(uint4*)adst0 = aw0;
        *(uint4*)(adst0 + 4) = aw1;
        #pragma unroll
        for (int i = 0; i < 4; i++) {
            *(uint2*)(bdst0 + i * BSTRH) =
                make_uint2(pack_bf16(bv[i].x, bv[i].y), pack_bf16(bv[i].z, bv[i].w));
        }
    }
    __syncthreads();

    for (int c = 0; c < nchunk; c++) {
        int buf = c & 1;
        bool has_next = (c + 1) < nchunk;
        uint4 aw0, aw1;
        float4 bv[4];
        if (has_next) {
            int k0w = (c + 1) << 4;   // pair-words per chunk = 16
            if (tokA >= 0) { aw0 = *(const uint4*)(aptr + k0w); aw1 = *(const uint4*)(aptr + k0w + 4); }
            else { aw0 = make_uint4(0u,0u,0u,0u); aw1 = aw0; }
            const float* bp = bptr + (size_t)((c + 1) << 5) * Nout;
            #pragma unroll
            for (int i = 0; i < 4; i++)
                bv[i] = *(const float4*)(bp + (size_t)i * Nout);
        }

        uint32_t abase = a_off + (uint32_t)buf * (ASTGW * 4);
        uint32_t bbase = b_off + (uint32_t)buf * (BSTGW * 4);
        #pragma unroll
        for (int ks = 0; ks < 2; ks++) {
            uint32_t a[2][4];
            LDSM_X4(a[0][0], a[0][1], a[0][2], a[0][3], abase + ks * 32);
            LDSM_X4(a[1][0], a[1][1], a[1][2], a[1][3], abase + 1280 + ks * 32);
            #pragma unroll
            for (int nip = 0; nip < 4; nip++) {
                uint32_t bA0, bA1, bB0, bB1;
                LDSM_T_X4(bA0, bA1, bB0, bB1, bbase + ks * 4352 + nip * 32);
                int niA = 2 * nip, niB = 2 * nip + 1;
                mma_bf16(acc[0][niA][0], acc[0][niA][1], acc[0][niA][2], acc[0][niA][3],
                         a[0][0], a[0][1], a[0][2], a[0][3], bA0, bA1);
                mma_bf16(acc[1][niA][0], acc[1][niA][1], acc[1][niA][2], acc[1][niA][3],
                         a[1][0], a[1][1], a[1][2], a[1][3], bA0, bA1);
                mma_bf16(acc[0][niB][0], acc[0][niB][1], acc[0][niB][2], acc[0][niB][3],
                         a[0][0], a[0][1], a[0][2], a[0][3], bB0, bB1);
                mma_bf16(acc[1][niB][0], acc[1][niB][1], acc[1][niB][2], acc[1][niB][3],
                         a[1][0], a[1][1], a[1][2], a[1][3], bB0, bB1);
            }
        }

        if (has_next) {
            int nb = buf ^ 1;
            uint32_t* adst = adst0 + nb * ASTGW;
            uint16_t* bdst = bdst0 + nb * (BSTGW * 2);
            *(uint4*)adst = aw0;
            *(uint4*)(adst + 4) = aw1;
            #pragma unroll
            for (int i = 0; i < 4; i++) {
                *(uint2*)(bdst + i * BSTRH) =
                    make_uint2(pack_bf16(bv[i].x, bv[i].y), pack_bf16(bv[i].z, bv[i].w));
            }
            __syncthreads();
        }
    }

    // ---- epilogue ----
    int tok[4]; float gwv[4];
    #pragma unroll
    for (int q = 0; q < 4; q++) {
        int r = row0 + warp_m * 32 + g + q * 8;
        tok[q] = perm[r];
        gwv[q] = (tok[q] >= 0) ? gw[tok[q]] : 0.f;
    }
    #pragma unroll
    for (int ni = 0; ni < 8; ni++) {
        int col = col0 + warp_n * 64 + ni * 8 + 2 * tg;
        float2 bs2 = *(const float2*)&bias[(size_t)e * Nout + col];
        bs2.x *= bsel; bs2.y *= bsel;
        #pragma unroll
        for (int mi = 0; mi < 2; mi++) {
            #pragma unroll
            for (int half2 = 0; half2 < 2; half2++) {
                int q = mi * 2 + half2;
                if (tok[q] < 0) continue;
                float v0 = (acc[mi][ni][half2 * 2 + 0] + bs2.x) * gwv[q];
                float v1 = (acc[mi][ni][half2 * 2 + 1] + bs2.y) * gwv[q];
                if (gelu_flag) {
                    float c0 = v0 + 0.044715f * v0 * v0 * v0;
                    v0 = 0.5f * v0 * (1.f + tanhf(0.7978845608028654f * c0));
                    float c1 = v1 + 0.044715f * v1 * v1 * v1;
                    v1 = 0.5f * v1 * (1.f + tanhf(0.7978845608028654f * c1));
                }
                if (out_bf16) {
                    ((uint32_t*)OutZ)[((size_t)tok[q] * Nout + col) >> 1] = pack_bf16(v0, v1);
                } else {
                    *(float2*)&OutZ[(size_t)tok[q] * Nout + col] = make_float2(v0, v1);
                }
            }
        }
    }
}

// ============ flash attention FA2: BQ=128, BK=64, bf16 in/out, ldmatrix ============
// qkv input is bf16 pair-words (row = 1536 words). ctx output bf16 pair-words.
#define QSTR 36
#define ATT5_SMEM_WORDS ((128 + 64 + 64) * QSTR + 64)

__global__ void __launch_bounds__(256, 2)
attn_mma(const uint32_t* __restrict__ qkv, const unsigned char* __restrict__ mask,
         uint32_t* __restrict__ ctx) {
    extern __shared__ uint32_t sm4[];
    uint32_t* Qs = sm4;
    uint32_t* Ks = Qs + 128 * QSTR;
    uint32_t* Vt = Ks + 64 * QSTR;
    float* maskS = (float*)(Vt + 64 * QSTR);

    int bh = blockIdx.y;
    int b = bh >> 4, h = bh & 15;
    int n0 = blockIdx.x << 7;
    int tid = threadIdx.x, lane = tid & 31, wid = tid >> 5;
    int g = lane >> 2, tg = lane & 3;
    int am0 = wid * 16 + g;

    uint32_t qaddr = smem_addr(Qs) +
        (uint32_t)((wid * 16 + (lane & 15)) * QSTR + ((lane >> 4) << 2)) * 4u;
    uint32_t bl_row = (uint32_t)((lane & 7) + ((lane >> 4) << 3));
    uint32_t bl_col = (uint32_t)(((lane >> 3) & 1) << 2);
    uint32_t kaddr = smem_addr(Ks) + (bl_row * QSTR + bl_col) * 4u;
    uint32_t vaddr = smem_addr(Vt) + (bl_row * QSTR + bl_col) * 4u;

    // ---- load Q tile (bf16 pair-words, straight copy) ----
    {
        int qrow = tid & 127, qp0 = (tid >> 7) << 4;   // 16 pair-words per thread
        const uint32_t* qp = qkv + (size_t)(b * 1024 + n0 + qrow) * 1536 + h * 32 + qp0;
        *(uint4*)&Qs[qrow * QSTR + qp0]      = *(const uint4*)(qp);
        *(uint4*)&Qs[qrow * QSTR + qp0 + 4]  = *(const uint4*)(qp + 4);
        *(uint4*)&Qs[qrow * QSTR + qp0 + 8]  = *(const uint4*)(qp + 8);
        *(uint4*)&Qs[qrow * QSTR + qp0 + 12] = *(const uint4*)(qp + 12);
    }

    float o[8][4];
    #pragma unroll
    for (int ni = 0; ni < 8; ni++)
        #pragma unroll
        for (int q = 0; q < 4; q++) o[ni][q] = 0.f;
    float m0 = -1e30f, m1 = -1e30f, l0 = 0.f, l1 = 0.f;

    int krow = tid & 63, kp0 = (tid >> 6) << 3;   // 64 rows x 8 pair-words
    int vkp = tid & 31, vd0 = (tid >> 5) << 3;    // 32 key-pairs x 8 d

    for (int kt = 0; kt < 16; kt++) {
        // ---- load K (copy) + V (transpose via byte_perm) + mask ----
        {
            const uint32_t* kp = qkv + (size_t)(b * 1024 + kt * 64 + krow) * 1536 + h * 32 + 512 + kp0;
            *(uint4*)&Ks[krow * QSTR + kp0]     = *(const uint4*)(kp);
            *(uint4*)&Ks[krow * QSTR + kp0 + 4] = *(const uint4*)(kp + 4);

            const uint32_t* v0p = qkv + (size_t)(b * 1024 + kt * 64 + 2 * vkp) * 1536 + h * 32 + 1024 + (vd0 >> 1);
            uint4 q0 = *(const uint4*)(v0p);
            uint4 q1 = *(const uint4*)(v0p + 1536);
            Vt[(vd0 + 0) * QSTR + vkp] = __byte_perm(q0.x, q1.x, 0x5410);
            Vt[(vd0 + 1) * QSTR + vkp] = __byte_perm(q0.x, q1.x, 0x7632);
            Vt[(vd0 + 2) * QSTR + vkp] = __byte_perm(q0.y, q1.y, 0x5410);
            Vt[(vd0 + 3) * QSTR + vkp] = __byte_perm(q0.y, q1.y, 0x7632);
            Vt[(vd0 + 4) * QSTR + vkp] = __byte_perm(q0.z, q1.z, 0x5410);
            Vt[(vd0 + 5) * QSTR + vkp] = __byte_perm(q0.z, q1.z, 0x7632);
            Vt[(vd0 + 6) * QSTR + vkp] = __byte_perm(q0.w, q1.w, 0x5410);
            Vt[(vd0 + 7) * QSTR + vkp] = __byte_perm(q0.w, q1.w, 0x7632);
            if (tid < 64)
                maskS[tid] = mask[b * 1024 + kt * 64 + tid] ? -10000.f : 0.f;
        }
        __syncthreads();

        float s[8][4];
        #pragma unroll
        for (int ni = 0; ni < 8; ni++)
            #pragma unroll
            for (int q = 0; q < 4; q++) s[ni][q] = 0.f;
        #pragma unroll
        for (int kb8 = 0; kb8 < 4; kb8++) {
            uint32_t a0, a1, a2, a3;
            LDSM_X4(a0, a1, a2, a3, qaddr + kb8 * 32);
            #pragma unroll
            for (int nip = 0; nip < 4; nip++) {
                uint32_t b0, b1, c0, c1;
                LDSM_X4(b0, b1, c0, c1, kaddr + nip * (16 * QSTR * 4) + kb8 * 32);
                int niA = 2 * nip, niB = 2 * nip + 1;
                mma_bf16(s[niA][0], s[niA][1], s[niA][2], s[niA][3], a0, a1, a2, a3, b0, b1);
                mma_bf16(s[niB][0], s[niB][1], s[niB][2], s[niB][3], a0, a1, a2, a3, c0, c1);
            }
        }
        #pragma unroll
        for (int ni = 0; ni < 8; ni++) {
            int c0 = ni * 8 + 2 * tg;
            float mv0 = maskS[c0], mv1 = maskS[c0 + 1];
            s[ni][0] = s[ni][0] * 0.125f + mv0;
            s[ni][1] = s[ni][1] * 0.125f + mv1;
            s[ni][2] = s[ni][2] * 0.125f + mv0;
            s[ni][3] = s[ni][3] * 0.125f + mv1;
        }

        float rm0 = -1e30f, rm1 = -1e30f;
        #pragma unroll
        for (int ni = 0; ni < 8; ni++) {
            rm0 = fmaxf(rm0, fmaxf(s[ni][0], s[ni][1]));
            rm1 = fmaxf(rm1, fmaxf(s[ni][2], s[ni][3]));
        }
        rm0 = fmaxf(rm0, __shfl_xor_sync(0xffffffffu, rm0, 1));
        rm0 = fmaxf(rm0, __shfl_xor_sync(0xffffffffu, rm0, 2));
        rm1 = fmaxf(rm1, __shfl_xor_sync(0xffffffffu, rm1, 1));
        rm1 = fmaxf(rm1, __shfl_xor_sync(0xffffffffu, rm1, 2));
        float mn0 = fmaxf(m0, rm0), mn1 = fmaxf(m1, rm1);
        float sc0 = __expf(m0 - mn0), sc1 = __expf(m1 - mn1);
        m0 = mn0; m1 = mn1;

        float ps0 = 0.f, ps1 = 0.f;
        #pragma unroll
        for (int ni = 0; ni < 8; ni++) {
            s[ni][0] = __expf(s[ni][0] - mn0);
            s[ni][1] = __expf(s[ni][1] - mn0);
            s[ni][2] = __expf(s[ni][2] - mn1);
            s[ni][3] = __expf(s[ni][3] - mn1);
            ps0 += s[ni][0] + s[ni][1];
            ps1 += s[ni][2] + s[ni][3];
        }
        ps0 += __shfl_xor_sync(0xffffffffu, ps0, 1);
        ps0 += __shfl_xor_sync(0xffffffffu, ps0, 2);
        ps1 += __shfl_xor_sync(0xffffffffu, ps1, 1);
        ps1 += __shfl_xor_sync(0xffffffffu, ps1, 2);
        l0 = l0 * sc0 + ps0;
        l1 = l1 * sc1 + ps1;

        #pragma unroll
        for (int ni = 0; ni < 8; ni++) {
            o[ni][0] *= sc0; o[ni][1] *= sc0;
            o[ni][2] *= sc1; o[ni][3] *= sc1;
        }

        #pragma unroll
        for (int kk = 0; kk < 4; kk++) {
            uint32_t a0 = pack_bf16(s[2 * kk][0],     s[2 * kk][1]);
            uint32_t a1 = pack_bf16(s[2 * kk][2],     s[2 * kk][3]);
            uint32_t a2 = pack_bf16(s[2 * kk + 1][0], s[2 * kk + 1][1]);
            uint32_t a3 = pack_bf16(s[2 * kk + 1][2], s[2 * kk + 1][3]);
            #pragma unroll
            for (int nip = 0; nip < 4; nip++) {
                uint32_t b0, b1, c0, c1;
                LDSM_X4(b0, b1, c0, c1, vaddr + nip * (16 * QSTR * 4) + kk * 32);
                int niA = 2 * nip, niB = 2 * nip + 1;
                mma_bf16(o[niA][0], o[niA][1], o[niA][2], o[niA][3], a0, a1, a2, a3, b0, b1);
                mma_bf16(o[niB][0], o[niB][1], o[niB][2], o[niB][3], a0, a1, a2, a3, c0, c1);
            }
        }
        __syncthreads();
    }

    // ---- write ctx (bf16 pair-words) ----
    float inv0 = 1.f / l0, inv1 = 1.f / l1;
    int t0 = b * 1024 + n0 + am0;
    int t1 = t0 + 8;
    #pragma unroll
    for (int ni = 0; ni < 8; ni++) {
        int c = ni * 8 + 2 * tg;
        ctx[((size_t)t0 * 1024 + h * 64 + c) >> 1] = pack_bf16(o[ni][0] * inv0, o[ni][1] * inv0);
        ctx[((size_t)t1 * 1024 + h * 64 + c) >> 1] = pack_bf16(o[ni][2] * inv1, o[ni][3] * inv1);
    }
}

// ---------------- residual + layernorm (+ optional bf16 mirror, optional fused gate) ----------------
__global__ void __launch_bounds__(256)
ln_kernel(const float* __restrict__ a, const float* __restrict__ parts, int nb,
          const float* __restrict__ s, const float* __restrict__ bias,
          float* __restrict__ out, uint32_t* __restrict__ outb,
          const float* __restrict__ Wg, int* __restrict__ gidx, float* __restrict__ ggw) {
    int t = blockIdx.x;
    int base = threadIdx.x << 2;
    size_t off = (size_t)t * DM + base;
    float4 av = *(const float4*)(a + off);
    float v[4] = {av.x, av.y, av.z, av.w};
    for (int p = 0; p < nb; p++) {
        float4 c = *(const float4*)(parts + (size_t)p * TKN * DM + off);
        v[0] += c.x; v[1] += c.y; v[2] += c.z; v[3] += c.w;
    }
    float s1 = v[0] + v[1] + v[2] + v[3];
    float s2 = v[0] * v[0] + v[1] * v[1] + v[2] * v[2] + v[3] * v[3];
    #pragma unroll
    for (int o = 16; o; o >>= 1) {
        s1 += __shfl_xor_sync(0xffffffffu, s1, o);
        s2 += __shfl_xor_sync(0xffffffffu, s2, o);
    }
    __shared__ float w1[8], w2[8];
    __shared__ float wlog[8][NE];
    __shared__ float sh_mean, sh_inv;
    int warp = threadIdx.x >> 5, lane = threadIdx.x & 31;
    if (lane == 0) { w1[warp] = s1; w2[warp] = s2; }
    __syncthreads();
    if (threadIdx.x == 0) {
        float A = 0.f, B = 0.f;
        #pragma unroll
        for (int i = 0; i < 8; i++) { A += w1[i]; B += w2[i]; }
        float mean = A * (1.f / DM);
        float var = B * (1.f / DM) - mean * mean;
        sh_mean = mean;
        sh_inv = rsqrtf(var + 1e-5f);
    }
    __syncthreads();
    float mean = sh_mean, inv = sh_inv;
    float4 sv = *(const float4*)(s + base);
    float4 biv = *(const float4*)(bias + base);
    float xr[4];
    xr[0] = (v[0] - mean) * inv * sv.x + biv.x;
    xr[1] = (v[1] - mean) * inv * sv.y + biv.y;
    xr[2] = (v[2] - mean) * inv * sv.z + biv.z;
    xr[3] = (v[3] - mean) * inv * sv.w + biv.w;
    *(float4*)(out + off) = make_float4(xr[0], xr[1], xr[2], xr[3]);
    if (outb) {
        *(uint2*)&outb[off >> 1] = make_uint2(pack_bf16(xr[0], xr[1]), pack_bf16(xr[2], xr[3]));
    }

    if (Wg) {
        float lg[NE];
        #pragma unroll
        for (int e2 = 0; e2 < NE; e2++) lg[e2] = 0.f;
        #pragma unroll
        for (int j = 0; j < 4; j++) {
            float4 w0 = *(const float4*)&Wg[(base + j) * NE];
            float4 wq = *(const float4*)&Wg[(base + j) * NE + 4];
            lg[0] += xr[j] * w0.x; lg[1] += xr[j] * w0.y;
            lg[2] += xr[j] * w0.z; lg[3] += xr[j] * w0.w;
            lg[4] += xr[j] * wq.x; lg[5] += xr[j] * wq.y;
            lg[6] += xr[j] * wq.z; lg[7] += xr[j] * wq.w;
        }
        #pragma unroll
        for (int e2 = 0; e2 < NE; e2++) {
            float q = lg[e2];
            #pragma unroll
            for (int o = 16; o; o >>= 1) q += __shfl_xor_sync(0xffffffffu, q, o);
            if (lane == 0) wlog[warp][e2] = q;
        }
        __syncthreads();
        if (threadIdx.x == 0) {
            float logits[NE];
            #pragma unroll
            for (int e2 = 0; e2 < NE; e2++) {
                float q = 0.f;
                #pragma unroll
                for (int w = 0; w < 8; w++) q += wlog[w][e2];
                logits[e2] = q;
            }
            float best = logits[0]; int bi = 0;
            #pragma unroll
            for (int e2 = 1; e2 < NE; e2++)
                if (logits[e2] > best) { best = logits[e2]; bi = e2; }
            float sum = 0.f;
            #pragma unroll
            for (int e2 = 0; e2 < NE; e2++) sum += expf(logits[e2] - best);
            gidx[t] = bi;
            ggw[t] = 1.f / sum;
        }
    }
}

// ---------------- launch ----------------
extern "C" void kernel_launch(void* const* d_in, const int* in_sizes, int n_in,
                              void* d_out, int out_size) {
    const float* src     = (const float*)d_in[0];
    const unsigned char* mask = (const unsigned char*)d_in[1];
    const float* Wg_attn = (const float*)d_in[2];
    const float* Wqkv    = (const float*)d_in[3];
    const float* bqkv    = (const float*)d_in[4];
    const float* Wo      = (const float*)d_in[5];
    const float* bo      = (const float*)d_in[6];
    const float* Wg_ffn  = (const float*)d_in[7];
    const float* W1      = (const float*)d_in[8];
    const float* b1      = (const float*)d_in[9];
    const float* W2      = (const float*)d_in[10];
    const float* b2      = (const float*)d_in[11];
    const float* ln1_s   = (const float*)d_in[12];
    const float* ln1_b   = (const float*)d_in[13];
    const float* ln2_s   = (const float*)d_in[14];
    const float* ln2_b   = (const float*)d_in[15];
    float* out = (float*)d_out;

    float *x, *tmp, *gw0, *gw1;
    uint32_t *srcb, *qkvb, *ctxb, *xb, *hb;
    int *idx0, *idx1, *perm0, *perm1, *te0, *te1;
    cudaGetSymbolAddress((void**)&srcb, g_srcb);
    cudaGetSymbolAddress((void**)&qkvb, g_qkvb);
    cudaGetSymbolAddress((void**)&ctxb, g_ctxb);
    cudaGetSymbolAddress((void**)&x,    g_x);
    cudaGetSymbolAddress((void**)&xb,   g_xb);
    cudaGetSymbolAddress((void**)&tmp,  g_tmp);
    cudaGetSymbolAddress((void**)&hb,   g_hb);
    cudaGetSymbolAddress((void**)&gw0,  g_gw0);
    cudaGetSymbolAddress((void**)&gw1,  g_gw1);
    cudaGetSymbolAddress((void**)&idx0, g_idx0);
    cudaGetSymbolAddress((void**)&idx1, g_idx1);
    cudaGetSymbolAddress((void**)&perm0, g_perm0);
    cudaGetSymbolAddress((void**)&perm1, g_perm1);
    cudaGetSymbolAddress((void**)&te0,  g_te0);
    cudaGetSymbolAddress((void**)&te1,  g_te1);

    int att_smem = ATT5_SMEM_WORDS * (int)sizeof(uint32_t);
    cudaFuncSetAttribute(attn_mma, cudaFuncAttributeMaxDynamicSharedMemorySize, att_smem);

    // 0. src -> bf16 pairs
    cvtb_kernel<<<TKN * DM / 4 / 256, 256>>>(src, srcb);
    // 1. attention gate + grouping
    gate_kernel<<<TKN, 256>>>(src, Wg_attn, idx0, gw0);
    scatter_kernel<<<1, 256>>>(idx0, perm0, te0);
    // 2. QKV projection -> bf16 qkv
    moe_gemm_mma<<<dim3(3 * DM / 128, MAXTILES, 1), 256>>>(
        srcb, Wqkv, bqkv, gw0, perm0, te0, (float*)qkvb, DM, 3 * DM, 0, DM, 1);
    // 3. attention (bf16 in/out)
    attn_mma<<<dim3(1024 / 128, 2 * NH), 256, att_smem>>>(qkvb, mask, ctxb);
    // 4. output projection, split-K x4 -> fp32 partials
    moe_gemm_mma<<<dim3(DM / 128, MAXTILES, 4), 256>>>(
        ctxb, Wo, bo, gw0, perm0, te0, tmp, DM, DM, 0, DM / 4, 0);
    // 5. x = LN1(src + 4 partials) + bf16 mirror + fused FFN gate
    ln_kernel<<<TKN, 256>>>(src, tmp, 4, ln1_s, ln1_b, x, xb, Wg_ffn, idx1, gw1);
    // 6. FFN grouping
    scatter_kernel<<<1, 256>>>(idx1, perm1, te1);
    // 7. h = gelu(gated W1) -> bf16 hbuf
    moe_gemm_mma<<<dim3(FFD / 128, MAXTILES, 1), 256>>>(
        xb, W1, b1, gw1, perm1, te1, (float*)hb, DM, FFD, 1, DM, 1);
    // 8. ffn = gated W2, split-K x8 -> fp32 partials
    moe_gemm_mma<<<dim3(DM / 128, MAXTILES, 8), 256>>>(
        hb, W2, b2, gw1, perm1, te1, tmp, FFD, DM, 0, FFD / 8, 0);
    // 9. out = LN2(x + 8 partials)
    ln_kernel<<<TKN, 256>>>(x, tmp, 8, ln2_s, ln2_b, out, nullptr, nullptr, nullptr, nullptr);
}